// round 8
// baseline (speedup 1.0000x reference)
#include <cuda_runtime.h>
#include <cuda_bf16.h>

// ---------------------------------------------------------------------------
// VQVAE forward. Encoder + VQ replicate XLA-CPU (Eigen) fp32 rounding order
// bit-for-bit so the argmin matches the reference; decoder is free-order fp32.
// R8: conv2 depth-2 LDG prefetch rotation; deconv1 16-ci weight chunks (4
// barrier pairs instead of 16) + pre-gathered x operands. No arithmetic
// changes anywhere.
// ---------------------------------------------------------------------------

#define BATCH 32
#define HID   128
#define EDIM  64
#define KCODES 512

typedef unsigned long long ull;

// scratch (device globals; no allocation allowed)
__device__ float g_h1[(size_t)BATCH * HID * 128 * 128];     // 268 MB
__device__ float g_z [(size_t)BATCH * EDIM * 64 * 64];      // 33.5 MB
__device__ float g_zq[(size_t)BATCH * EDIM * 64 * 64];      // 33.5 MB (z_q_st)
__device__ float g_d1[(size_t)BATCH * HID * 128 * 128];     // 268 MB
__device__ float g_wT2[16 * 128 * 64];                      // conv2 w: [tap][ci][co]
__device__ float g_wr1[4 * 64 * 4 * 128];                   // dec_w1: [p][ci][tap][co]
__device__ float g_wr2[128 * 4 * 3 * 4];                    // dec_w2: [ci][p][co][tap4]
__device__ float g_cn[KCODES];                              // ||code||^2 (ref rounding)

// ---------------------------------------------------------------------------
// f32x2 helpers: two independent IEEE fp32 ops per instruction.
// ---------------------------------------------------------------------------
__device__ __forceinline__ unsigned smem_u32(const void* p) {
    unsigned a;
    asm("{ .reg .u64 t; cvta.to.shared.u64 t, %1; cvt.u32.u64 %0, t; }"
        : "=r"(a) : "l"(p));
    return a;
}
__device__ __forceinline__ ull pk2(float f) {
    ull d; unsigned u = __float_as_uint(f);
    asm("mov.b64 %0, {%1, %1};" : "=l"(d) : "r"(u));
    return d;
}
__device__ __forceinline__ ull pk2ab(float lo, float hi) {
    ull d;
    asm("mov.b64 %0, {%1, %2};" : "=l"(d)
        : "r"(__float_as_uint(lo)), "r"(__float_as_uint(hi)));
    return d;
}
__device__ __forceinline__ void fma2(ull& acc, ull a, ull b) {
    asm("fma.rn.f32x2 %0, %1, %2, %0;" : "+l"(acc) : "l"(a), "l"(b));
}
__device__ __forceinline__ void lds2(ull& a, ull& b, unsigned addr) {
    asm("ld.shared.v2.b64 {%0, %1}, [%2];" : "=l"(a), "=l"(b) : "r"(addr));
}
__device__ __forceinline__ void upk2(float& lo, float& hi, ull v) {
    unsigned l, h;
    asm("mov.b64 {%0, %1}, %2;" : "=r"(l), "=r"(h) : "l"(v));
    lo = __uint_as_float(l); hi = __uint_as_float(h);
}

// ---------------------------------------------------------------------------
// prep: codebook norms (separate mul+add sequential — XLA reduce), conv2 weight
// transpose [tap][ci][co], deconv weight rearrangement.
// ---------------------------------------------------------------------------
__global__ void prep_k(const float* __restrict__ cb,
                       const float* __restrict__ ew2,
                       const float* __restrict__ dw1,
                       const float* __restrict__ dw2) {
    int t = blockIdx.x * blockDim.x + threadIdx.x;
    int stride = gridDim.x * blockDim.x;
    if (t < KCODES) {
        float s = 0.f;
        for (int d = 0; d < EDIM; d++) {
            float v = cb[t * EDIM + d];
            s = __fadd_rn(s, __fmul_rn(v, v));
        }
        g_cn[t] = s;
    }
    for (int e = t; e < 16 * 128 * 64; e += stride) {
        int tap = e >> 13;
        int ci  = (e >> 6) & 127;
        int co  = e & 63;
        g_wT2[e] = ew2[(size_t)co * 2048 + ci * 16 + tap];
    }
    // wr1: [p][ci][tap][co]; tap j = jh*2+jw pairs with input patch elem (jh,jw),
    // src kernel element (ph+2jh, pw+2jw), p = ph*2+pw.
    for (int e = t; e < 4 * 64 * 4 * 128; e += stride) {
        int co  = e & 127;
        int tap = (e >> 7) & 3;
        int ci  = (e >> 9) & 63;
        int p   = e >> 15;
        int ph = p >> 1, pw = p & 1;
        int jh = tap >> 1, jw = tap & 1;
        g_wr1[e] = dw1[((size_t)co * 64 + ci) * 16 + (ph + 2 * jh) * 4 + (pw + 2 * jw)];
    }
    // wr2: [ci][p][co][tap4]
    for (int e = t; e < 128 * 4 * 3; e += stride) {
        int ci  = e / 12;
        int rem = e % 12;
        int p   = rem / 3;
        int co  = rem % 3;
        int ph = p >> 1, pw = p & 1;
        const float* src = dw2 + ((size_t)co * 128 + ci) * 16;
        float* dst = g_wr2 + (size_t)e * 4;
        dst[0] = src[ ph      * 4 +  pw     ];
        dst[1] = src[ ph      * 4 + (pw + 2)];
        dst[2] = src[(ph + 2) * 4 +  pw     ];
        dst[3] = src[(ph + 2) * 4 + (pw + 2)];
    }
}

// ---------------------------------------------------------------------------
// conv1 (FFMA2): x[32,3,256,256] -> relu -> h1[32,128,128,128], k=4 s=2 p=1.
// Per-co chain unchanged: k = tap*3+ci ascending, single fmaf chain, bias
// after. co packed in pairs; weights in smem as [k48][co128].
// ---------------------------------------------------------------------------
__global__ __launch_bounds__(256) void conv1_k(const float* __restrict__ x,
                                               const float* __restrict__ w,
                                               const float* __restrict__ bias) {
    __shared__ __align__(16) float sWT[48 * 128];   // [k][co]
    __shared__ float sX[3 * 34 * 34];
    int b = blockIdx.z, oht = blockIdx.y, owt = blockIdx.x;
    int t = threadIdx.x;
    for (int i = t; i < 6144; i += 256) {
        int k = i >> 7, co = i & 127;
        int tap = k / 3, ci = k - tap * 3;
        sWT[i] = w[co * 48 + ci * 16 + tap];
    }
    int ih0 = oht * 32 - 1, iw0 = owt * 32 - 1;
    const float* xb = x + (size_t)b * 3 * 256 * 256;
    for (int i = t; i < 3 * 1156; i += 256) {
        int ci = i / 1156, r = (i % 1156) / 34, c = i % 34;
        int ih = ih0 + r, iw = iw0 + c;
        sX[i] = ((unsigned)ih < 256u && (unsigned)iw < 256u)
                ? xb[((size_t)ci * 256 + ih) * 256 + iw] : 0.f;
    }
    __syncthreads();
    int oh_l = t >> 4, ow_l = t & 15;
    float xw[48];
    #pragma unroll
    for (int kh = 0; kh < 4; kh++)
        #pragma unroll
        for (int kw = 0; kw < 4; kw++)
            #pragma unroll
            for (int ci = 0; ci < 3; ci++)
                xw[(kh * 4 + kw) * 3 + ci] =
                    sX[ci * 1156 + (2 * oh_l + kh) * 34 + (2 * ow_l + kw)];
    int oh = oht * 16 + oh_l, ow = owt * 16 + ow_l;
    size_t obase = (size_t)b * 2097152 + (size_t)oh * 128 + ow;
    unsigned swt = smem_u32(sWT);
    #pragma unroll 2
    for (int g = 0; g < 8; g++) {          // 16 co per group
        ull acc[8];
        #pragma unroll
        for (int j = 0; j < 8; j++) acc[j] = 0ull;
        #pragma unroll
        for (int k = 0; k < 48; k++) {
            ull X = pk2(xw[k]);
            unsigned a = swt + k * 512 + g * 64;
            ull w0, w1, w2, w3, w4, w5, w6, w7;
            lds2(w0, w1, a);
            lds2(w2, w3, a + 16);
            lds2(w4, w5, a + 32);
            lds2(w6, w7, a + 48);
            fma2(acc[0], X, w0); fma2(acc[1], X, w1);
            fma2(acc[2], X, w2); fma2(acc[3], X, w3);
            fma2(acc[4], X, w4); fma2(acc[5], X, w5);
            fma2(acc[6], X, w6); fma2(acc[7], X, w7);
        }
        #pragma unroll
        for (int j = 0; j < 8; j++) {
            int co = g * 16 + 2 * j;
            float lo, hi;
            upk2(lo, hi, acc[j]);
            float v0 = __fadd_rn(lo, __ldg(bias + co));
            float v1 = __fadd_rn(hi, __ldg(bias + co + 1));
            g_h1[obase + (size_t)co * 16384]       = fmaxf(v0, 0.f);
            g_h1[obase + (size_t)(co + 1) * 16384] = fmaxf(v1, 0.f);
        }
    }
}

// ---------------------------------------------------------------------------
// conv2 (FFMA2, 4 outputs/thread, depth-2 prefetch): h1 -> z[32,64,64,64].
// Per-co chain unchanged (taps row-major outer, ci inner). x via __ldg with
// explicit 2-iteration prefetch rotation; per-tap weights in smem.
// ---------------------------------------------------------------------------
__global__ __launch_bounds__(256) void conv2_k(const float* __restrict__ bias) {
    __shared__ __align__(16) float sW[8192];   // [ci][co] for current tap
    int b = blockIdx.z, oht = blockIdx.y, owt = blockIdx.x;
    int t = threadIdx.x;
    int tq = t & 3;
    int s  = t >> 2;
    int row = s >> 3;
    int cp  = s & 7;
    int oh  = oht * 8 + row;
    int ow0 = owt * 32 + cp * 4;
    const float* h1b = g_h1 + (size_t)b * 2097152;
    ull A0[8], A1[8], A2[8], A3[8];
    #pragma unroll
    for (int j = 0; j < 8; j++) { A0[j] = 0ull; A1[j] = 0ull; A2[j] = 0ull; A3[j] = 0ull; }
    unsigned swu = smem_u32(sW) + tq * 64;
    for (int tap = 0; tap < 16; tap++) {
        __syncthreads();
        {
            const float4* src = (const float4*)(g_wT2 + tap * 8192);
            float4* dst = (float4*)sW;
            #pragma unroll
            for (int i = 0; i < 8; i++) dst[t + 256 * i] = src[t + 256 * i];
        }
        __syncthreads();
        int kh = tap >> 2, kw = tap & 3;
        int ih  = 2 * oh + kh - 1;
        int iw0 = 2 * ow0 + kw - 1;
        bool hok = ((unsigned)ih < 128u);
        bool q0 = hok && ((unsigned)iw0 < 128u);
        bool q1 = hok && ((unsigned)(iw0 + 2) < 128u);
        bool q2 = hok && ((unsigned)(iw0 + 4) < 128u);
        bool q3 = hok && ((unsigned)(iw0 + 6) < 128u);
        const float* xp = h1b + (size_t)ih * 128 + iw0;
        // depth-2 prefetch rotation: cur (c) / next (n) / next-next loaded in loop
        float c0 = q0 ? __ldg(xp)     : 0.f;
        float c1 = q1 ? __ldg(xp + 2) : 0.f;
        float c2 = q2 ? __ldg(xp + 4) : 0.f;
        float c3 = q3 ? __ldg(xp + 6) : 0.f;
        float n0 = q0 ? __ldg(xp + 16384)     : 0.f;
        float n1 = q1 ? __ldg(xp + 16384 + 2) : 0.f;
        float n2 = q2 ? __ldg(xp + 16384 + 4) : 0.f;
        float n3 = q3 ? __ldg(xp + 16384 + 6) : 0.f;
        #pragma unroll 2
        for (int ci = 0; ci < 128; ci++) {
            float m0 = 0.f, m1 = 0.f, m2 = 0.f, m3 = 0.f;
            if (ci < 126) {
                const float* xn = xp + (size_t)(ci + 2) * 16384;
                m0 = q0 ? __ldg(xn)     : 0.f;
                m1 = q1 ? __ldg(xn + 2) : 0.f;
                m2 = q2 ? __ldg(xn + 4) : 0.f;
                m3 = q3 ? __ldg(xn + 6) : 0.f;
            }
            ull X0 = pk2(c0), X1 = pk2(c1), X2 = pk2(c2), X3 = pk2(c3);
            unsigned a = swu + ci * 256;
            ull w0, w1, w2, w3, w4, w5, w6, w7;
            lds2(w0, w1, a);
            lds2(w2, w3, a + 16);
            lds2(w4, w5, a + 32);
            lds2(w6, w7, a + 48);
            fma2(A0[0], X0, w0); fma2(A0[1], X0, w1);
            fma2(A0[2], X0, w2); fma2(A0[3], X0, w3);
            fma2(A0[4], X0, w4); fma2(A0[5], X0, w5);
            fma2(A0[6], X0, w6); fma2(A0[7], X0, w7);
            fma2(A1[0], X1, w0); fma2(A1[1], X1, w1);
            fma2(A1[2], X1, w2); fma2(A1[3], X1, w3);
            fma2(A1[4], X1, w4); fma2(A1[5], X1, w5);
            fma2(A1[6], X1, w6); fma2(A1[7], X1, w7);
            fma2(A2[0], X2, w0); fma2(A2[1], X2, w1);
            fma2(A2[2], X2, w2); fma2(A2[3], X2, w3);
            fma2(A2[4], X2, w4); fma2(A2[5], X2, w5);
            fma2(A2[6], X2, w6); fma2(A2[7], X2, w7);
            fma2(A3[0], X3, w0); fma2(A3[1], X3, w1);
            fma2(A3[2], X3, w2); fma2(A3[3], X3, w3);
            fma2(A3[4], X3, w4); fma2(A3[5], X3, w5);
            fma2(A3[6], X3, w6); fma2(A3[7], X3, w7);
            c0 = n0; c1 = n1; c2 = n2; c3 = n3;
            n0 = m0; n1 = m1; n2 = m2; n3 = m3;
        }
    }
    size_t ob = (size_t)b * 262144 + (size_t)oh * 64 + ow0;
    #pragma unroll
    for (int j = 0; j < 8; j++) {
        int co0 = tq * 16 + 2 * j;
        float bv0 = __ldg(bias + co0), bv1 = __ldg(bias + co0 + 1);
        float lo, hi;
        size_t o0 = ob + (size_t)co0 * 4096;
        size_t o1 = ob + (size_t)(co0 + 1) * 4096;
        upk2(lo, hi, A0[j]); g_z[o0]     = __fadd_rn(lo, bv0); g_z[o1]     = __fadd_rn(hi, bv1);
        upk2(lo, hi, A1[j]); g_z[o0 + 1] = __fadd_rn(lo, bv0); g_z[o1 + 1] = __fadd_rn(hi, bv1);
        upk2(lo, hi, A2[j]); g_z[o0 + 2] = __fadd_rn(lo, bv0); g_z[o1 + 2] = __fadd_rn(hi, bv1);
        upk2(lo, hi, A3[j]); g_z[o0 + 3] = __fadd_rn(lo, bv0); g_z[o1 + 3] = __fadd_rn(hi, bv1);
    }
}

// ---------------------------------------------------------------------------
// VQ assign + z_q scatter (FFMA2). Per-code chain preserved exactly; thread
// handles 2 z-vectors sharing the codebook LDS stream, then writes
// z_q_st = fl(z + fl(q - z)) directly.
// ---------------------------------------------------------------------------
__global__ __launch_bounds__(256) void vq_k(const float* __restrict__ cb) {
    __shared__ __align__(16) float sC[128 * 64];  // [pair][e][2]
    __shared__ float sN[128];
    int gid = blockIdx.x * 256 + threadIdx.x;
    int u0 = gid, u1 = gid + 65536;
    float zA[64], zB[64];
    {
        const float4* zp = (const float4*)(g_z + (size_t)u0 * 64);
        #pragma unroll
        for (int q = 0; q < 16; q++) {
            float4 f = zp[q];
            zA[q * 4 + 0] = f.x; zA[q * 4 + 1] = f.y;
            zA[q * 4 + 2] = f.z; zA[q * 4 + 3] = f.w;
        }
        const float4* zp2 = (const float4*)(g_z + (size_t)u1 * 64);
        #pragma unroll
        for (int q = 0; q < 16; q++) {
            float4 f = zp2[q];
            zB[q * 4 + 0] = f.x; zB[q * 4 + 1] = f.y;
            zB[q * 4 + 2] = f.z; zB[q * 4 + 3] = f.w;
        }
    }
    float zzA = 0.f, zzB = 0.f;
    #pragma unroll
    for (int e = 0; e < 64; e++) {
        zzA = __fadd_rn(zzA, __fmul_rn(zA[e], zA[e]));
        zzB = __fadd_rn(zzB, __fmul_rn(zB[e], zB[e]));
    }
    float bestA = 3.4e38f, bestB = 3.4e38f;
    int biA = 0, biB = 0;
    unsigned scu = smem_u32(sC);
    for (int ch = 0; ch < 4; ch++) {
        __syncthreads();
        const float* src = cb + (size_t)ch * 8192;
        for (int i = threadIdx.x; i < 8192; i += 256) {
            int pr = i >> 7, r = i & 127, e = r >> 1, s2 = r & 1;
            sC[i] = src[(2 * pr + s2) * 64 + e];
        }
        if (threadIdx.x < 128) sN[threadIdx.x] = g_cn[ch * 128 + threadIdx.x];
        __syncthreads();
        for (int kk = 0; kk < 128; kk += 16) {      // 8 pairs = 16 codes
            ull SA[8], SB[8];
            #pragma unroll
            for (int pp = 0; pp < 8; pp++) { SA[pp] = 0ull; SB[pp] = 0ull; }
            unsigned base = scu + (kk >> 1) * 512;
            #pragma unroll
            for (int e = 0; e < 64; e += 2) {
                ull ZA0 = pk2(zA[e]), ZA1 = pk2(zA[e + 1]);
                ull ZB0 = pk2(zB[e]), ZB1 = pk2(zB[e + 1]);
                #pragma unroll
                for (int pp = 0; pp < 8; pp++) {
                    ull w0, w1;
                    lds2(w0, w1, base + pp * 512 + e * 8);
                    fma2(SA[pp], ZA0, w0);
                    fma2(SA[pp], ZA1, w1);
                    fma2(SB[pp], ZB0, w0);
                    fma2(SB[pp], ZB1, w1);
                }
            }
            #pragma unroll
            for (int pp = 0; pp < 8; pp++) {
                int k0 = kk + 2 * pp;
                float n0 = sN[k0], n1 = sN[k0 + 1];
                float s0, s1;
                upk2(s0, s1, SA[pp]);
                float d0 = __fadd_rn(__fadd_rn(zzA, -2.f * s0), n0);
                float d1 = __fadd_rn(__fadd_rn(zzA, -2.f * s1), n1);
                if (d0 < bestA) { bestA = d0; biA = ch * 128 + k0; }
                if (d1 < bestA) { bestA = d1; biA = ch * 128 + k0 + 1; }
                upk2(s0, s1, SB[pp]);
                d0 = __fadd_rn(__fadd_rn(zzB, -2.f * s0), n0);
                d1 = __fadd_rn(__fadd_rn(zzB, -2.f * s1), n1);
                if (d0 < bestB) { bestB = d0; biB = ch * 128 + k0; }
                if (d1 < bestB) { bestB = d1; biB = ch * 128 + k0 + 1; }
            }
        }
    }
    {
        const float* c = cb + (size_t)biA * 64;
        size_t base = (size_t)(u0 >> 12) * 262144 + (u0 & 4095);
        #pragma unroll 8
        for (int e = 0; e < 64; e++) {
            float zv = zA[e];
            g_zq[base + (size_t)e * 4096] =
                __fadd_rn(zv, __fadd_rn(__ldg(c + e), -zv));
        }
        const float* c2 = cb + (size_t)biB * 64;
        size_t base2 = (size_t)(u1 >> 12) * 262144 + (u1 & 4095);
        #pragma unroll 8
        for (int e = 0; e < 64; e++) {
            float zv = zB[e];
            g_zq[base2 + (size_t)e * 4096] =
                __fadd_rn(zv, __fadd_rn(__ldg(c2 + e), -zv));
        }
    }
}

// ---------------------------------------------------------------------------
// deconv1 (FFMA2): zq_st -> relu -> d1. Parity-decomposed; thread = 2 outputs
// (ow, ow+16) x 32 co (pair-packed). Weights staged 16 ci per sync (4 barrier
// pairs/block), p-stride padded to 2056 floats (p lanes at banks 0/8/16/24).
// x operands pre-gathered into packed regs per ci before the fma2 burst.
// ---------------------------------------------------------------------------
extern __shared__ float dsm1[];
__global__ __launch_bounds__(256, 2) void deconv1_k(const float* __restrict__ bias) {
    float* sX = dsm1;                 // [ci64][10][18] = 11520 floats
    float* sW = dsm1 + 11520;         // [p][(c*4+tap)*32 + co], stride 2056/p
    __shared__ float sB[32];
    int bz = blockIdx.z;
    int b = bz >> 2, coq = bz & 3;
    int oht = blockIdx.y, owt = blockIdx.x;
    int t = threadIdx.x;
    if (t < 32) sB[t] = bias[coq * 32 + t];
    int r0 = oht * 8 - 1, c0 = owt * 16 - 1;
    const float* zq = g_zq + (size_t)b * 262144;
    for (int i = t; i < 11520; i += 256) {
        int ci = i / 180, rem = i % 180;
        int rr = rem / 18, cc = rem % 18;
        int ih = r0 + rr, iw = c0 + cc;
        sX[i] = ((unsigned)ih < 64u && (unsigned)iw < 64u)
                ? zq[(size_t)ci * 4096 + ih * 64 + iw] : 0.f;
    }
    __syncthreads();
    int oh_l = t >> 4, ow_l = t & 15;
    int ph = oh_l & 1, pw = ow_l & 1, p = ph * 2 + pw;
    int xr = (oh_l >> 1) + ph;
    int xc = (ow_l >> 1) + pw;
    ull acc0[16], acc1[16];
    #pragma unroll
    for (int j = 0; j < 16; j++) {
        ull bv = pk2ab(sB[2 * j], sB[2 * j + 1]);
        acc0[j] = bv; acc1[j] = bv;
    }
    unsigned swu = smem_u32(sW) + p * 8224;        // p stride 2056 floats
    for (int cc16 = 0; cc16 < 4; cc16++) {
        __syncthreads();
        for (int i = t; i < 2048; i += 256) {      // 2048 float4 = 8192 floats
            int pp = i >> 9, rem = i & 511;
            int c = rem >> 5, rem2 = rem & 31;
            int tap = rem2 >> 3, f4 = rem2 & 7;
            float4 v = ((const float4*)g_wr1)[
                (size_t)(((pp * 64 + cc16 * 16 + c) * 4 + tap)) * 32 + coq * 8 + f4];
            *(float4*)(sW + pp * 2056 + (c * 4 + tap) * 32 + f4 * 4) = v;
        }
        __syncthreads();
        #pragma unroll 2
        for (int c = 0; c < 16; c++) {
            int xb = (cc16 * 16 + c) * 180;
            // pre-gather all 8 x operands (4 taps x 2 outputs), packed
            ull X0[4], X1[4];
            #pragma unroll
            for (int tap = 0; tap < 4; tap++) {
                int xi = xb + (xr + (tap >> 1)) * 18 + xc + (tap & 1);
                X0[tap] = pk2(sX[xi]);
                X1[tap] = pk2(sX[xi + 8]);
            }
            #pragma unroll
            for (int tap = 0; tap < 4; tap++) {
                unsigned a = swu + (c * 4 + tap) * 128;
                #pragma unroll
                for (int j = 0; j < 8; j++) {
                    ull w0, w1;
                    lds2(w0, w1, a + j * 16);
                    fma2(acc0[2 * j],     X0[tap], w0);
                    fma2(acc0[2 * j + 1], X0[tap], w1);
                    fma2(acc1[2 * j],     X1[tap], w0);
                    fma2(acc1[2 * j + 1], X1[tap], w1);
                }
            }
        }
    }
    int oh = oht * 16 + oh_l, ow = owt * 32 + ow_l;
    size_t obase = (size_t)b * 2097152 + (size_t)(coq * 32) * 16384
                 + (size_t)oh * 128 + ow;
    #pragma unroll
    for (int j = 0; j < 16; j++) {
        float lo, hi;
        upk2(lo, hi, acc0[j]);
        g_d1[obase + (size_t)(2 * j) * 16384]     = fmaxf(lo, 0.f);
        g_d1[obase + (size_t)(2 * j + 1) * 16384] = fmaxf(hi, 0.f);
        upk2(lo, hi, acc1[j]);
        g_d1[obase + (size_t)(2 * j) * 16384 + 16]     = fmaxf(lo, 0.f);
        g_d1[obase + (size_t)(2 * j + 1) * 16384 + 16] = fmaxf(hi, 0.f);
    }
}

// ---------------------------------------------------------------------------
// deconv2 (FFMA2 tap-split): d1 -> out[32,3,256,256]. acc lanes = tap parities
// {0,2}/{1,3}, summed at the end (decoder rounding free).
// ---------------------------------------------------------------------------
__global__ __launch_bounds__(256) void deconv2_k(const float* __restrict__ bias,
                                                 float* __restrict__ out) {
    __shared__ float sX[32 * 100];
    __shared__ __align__(16) float sW[32 * 4 * 3 * 4];   // [ci][p][co][tap4]
    int b = blockIdx.z, oht = blockIdx.y, owt = blockIdx.x;
    int t = threadIdx.x;
    int r0 = oht * 8 - 1, c0 = owt * 8 - 1;
    int oh_l = t >> 4, ow_l = t & 15;
    int ph = oh_l & 1, pw = ow_l & 1, p = ph * 2 + pw;
    int xr = (oh_l >> 1) + ph;
    int xc = (ow_l >> 1) + pw;
    const float* d1b = g_d1 + (size_t)b * 2097152;
    ull a0 = 0ull, a1 = 0ull, a2 = 0ull;
    unsigned swu = smem_u32(sW) + p * 48;
    for (int chn = 0; chn < 4; chn++) {
        __syncthreads();
        for (int i = t; i < 3200; i += 256) {
            int ci = i / 100, rr = (i % 100) / 10, cc = i % 10;
            int ih = r0 + rr, iw = c0 + cc;
            sX[i] = ((unsigned)ih < 128u && (unsigned)iw < 128u)
                    ? d1b[(size_t)(chn * 32 + ci) * 16384 + ih * 128 + iw] : 0.f;
        }
        for (int i = t; i < 384; i += 256) {
            int ci = i / 12, rem = i % 12;
            ((float4*)sW)[i] =
                ((const float4*)g_wr2)[(size_t)(chn * 32 + ci) * 12 + rem];
        }
        __syncthreads();
        #pragma unroll 4
        for (int ci = 0; ci < 32; ci++) {
            int base = ci * 100;
            ull XA = pk2ab(sX[base + xr * 10 + xc], sX[base + xr * 10 + xc + 1]);
            ull XB = pk2ab(sX[base + (xr + 1) * 10 + xc],
                           sX[base + (xr + 1) * 10 + xc + 1]);
            unsigned a = swu + ci * 192;
            ull w01, w23, v01, v23, u01, u23;
            lds2(w01, w23, a);
            lds2(v01, v23, a + 16);
            lds2(u01, u23, a + 32);
            fma2(a0, XA, w01); fma2(a0, XB, w23);
            fma2(a1, XA, v01); fma2(a1, XB, v23);
            fma2(a2, XA, u01); fma2(a2, XB, u23);
        }
    }
    int oh = oht * 16 + oh_l, ow = owt * 16 + ow_l;
    size_t obase = (size_t)b * 3 * 65536 + (size_t)oh * 256 + ow;
    float lo, hi;
    upk2(lo, hi, a0); out[obase]             = (lo + hi) + __ldg(bias + 0);
    upk2(lo, hi, a1); out[obase + 65536]     = (lo + hi) + __ldg(bias + 1);
    upk2(lo, hi, a2); out[obase + 2 * 65536] = (lo + hi) + __ldg(bias + 2);
}

// ---------------------------------------------------------------------------
extern "C" void kernel_launch(void* const* d_in, const int* in_sizes, int n_in,
                              void* d_out, int out_size) {
    const float* x      = (const float*)d_in[0];
    const float* enc_w1 = (const float*)d_in[1];
    const float* enc_b1 = (const float*)d_in[2];
    const float* enc_w2 = (const float*)d_in[3];
    const float* enc_b2 = (const float*)d_in[4];
    const float* dec_w1 = (const float*)d_in[5];
    const float* dec_b1 = (const float*)d_in[6];
    const float* dec_w2 = (const float*)d_in[7];
    const float* dec_b2 = (const float*)d_in[8];
    const float* cb     = (const float*)d_in[9];
    float* out = (float*)d_out;

    cudaFuncSetAttribute(deconv1_k, cudaFuncAttributeMaxDynamicSharedMemorySize,
                         (11520 + 4 * 2056) * 4);

    prep_k<<<64, 256>>>(cb, enc_w2, dec_w1, dec_w2);
    conv1_k<<<dim3(8, 8, BATCH), 256>>>(x, enc_w1, enc_b1);
    conv2_k<<<dim3(2, 8, BATCH), 256>>>(enc_b2);
    vq_k<<<256, 256>>>(cb);
    deconv1_k<<<dim3(4, 8, BATCH * 4), 256, (11520 + 4 * 2056) * 4>>>(dec_b1);
    deconv2_k<<<dim3(16, 16, BATCH), 256>>>(dec_b2, out);
}